// round 1
// baseline (speedup 1.0000x reference)
#include <cuda_runtime.h>

// Problem constants (fixed shapes from setup_inputs)
#define B_   8
#define CIN  16
#define OC_  16
#define CG   192    // Cin*12
#define OG   192    // O*12
#define HP   66
#define WP   322
#define HC   64     // conv output rows
#define WC   320    // conv output cols

// Conv tiling
#define TO   64     // out-channel tile
#define TX   64     // x tile
#define CC   8      // input channels per smem chunk
#define NTHREADS 128

// Packed weights: Kt[cg][tap(7)][og]  (og contiguous for coalesced access)
__device__ float g_Kt[CG * 7 * OG];

// ---------------------------------------------------------------------------
// Kernel 1: expand weight (O,Cin,12,7) -> Kt[cg][k][og] using p6m group tables
// perm[g,h]: gi = inv(g); compose(gi, h)
//   fg==0: r = (rh - rg) mod 6 ; fg==1: r = (rg - rh) mod 6 ; f = fg ^ fh
// tap_src[g,0]=0 ; tap_src[g,1+i] = 1 + ((fg==0) ? (i-rg) mod 6 : (rg-i) mod 6)
// ---------------------------------------------------------------------------
__global__ void prep_kernel(const float* __restrict__ w) {
    int tid = blockIdx.x * blockDim.x + threadIdx.x;
    if (tid >= CG * OG) return;
    int cg = tid / OG;
    int og = tid % OG;
    int o = og / 12, g = og % 12;
    int c = cg / 12, h = cg % 12;
    int fg = g / 6, rg = g % 6;
    int fh = h / 6, rh = h % 6;
    int f = fg ^ fh;
    int r = (fg == 0) ? ((rh - rg + 6) % 6) : ((rg - rh + 6) % 6);
    int p = f * 6 + r;
    const float* wp = w + ((o * CIN + c) * 12 + p) * 7;
#pragma unroll
    for (int k = 0; k < 7; k++) {
        int tap;
        if (k == 0) {
            tap = 0;
        } else {
            int i = k - 1;
            int src = (fg == 0) ? ((i - rg + 12) % 6) : ((rg - i + 12) % 6);
            tap = 1 + src;
        }
        g_Kt[(cg * 7 + k) * OG + og] = wp[tap];
    }
}

// ---------------------------------------------------------------------------
// Kernel 2: direct 7-tap hex conv, writes interior of res (y=1..64, x=1..320)
// Hex tap offsets (py,px) in the 3x3 window: positions of _HEX_POS
// ---------------------------------------------------------------------------
__global__ __launch_bounds__(NTHREADS) void conv_kernel(
    const float* __restrict__ x,
    const float* __restrict__ bias,
    float* __restrict__ out)
{
    // padded x row (68) so each row base stays 16B-aligned for LDS.128
    __shared__ float xs[CC][3][68];
    __shared__ float ws[CC][7][TO];

    const int bz  = blockIdx.z;
    const int b   = bz / 3;
    const int ogt = bz % 3;
    const int cy  = blockIdx.y;           // conv row 0..63
    const int x0  = TX * blockIdx.x;      // conv col base 0..256

    const int tid = threadIdx.x;
    const int to  = tid >> 4;             // 0..7  -> 8 out channels each
    const int tp  = tid & 15;             // 0..15 -> 4 pixels each
    const int ogl = to * 8;
    const int pxl = tp * 4;

    const int og0 = ogt * TO;
    const float* xb = x + (size_t)b * CG * HP * WP;

    float acc[8][4];
#pragma unroll
    for (int i = 0; i < 8; i++)
#pragma unroll
        for (int j = 0; j < 4; j++) acc[i][j] = 0.f;

    const int hpy[7] = {1, 0, 0, 1, 2, 2, 1};
    const int hpx[7] = {1, 0, 1, 2, 2, 1, 0};

    for (int cg0 = 0; cg0 < CG; cg0 += CC) {
        // --- load x chunk: CC channels x 3 rows x 66 cols ---
        for (int i = tid; i < CC * 3 * 66; i += NTHREADS) {
            int c   = i / 198;
            int rem = i % 198;
            int row = rem / 66;
            int col = rem % 66;
            xs[c][row][col] = xb[((size_t)(cg0 + c) * HP + (cy + row)) * WP + x0 + col];
        }
        // --- load weight chunk: CC x 7 x 64 ---
        for (int i = tid; i < CC * 7 * TO; i += NTHREADS) {
            int c   = i / (7 * TO);
            int rem = i % (7 * TO);
            int k   = rem / TO;
            int j   = rem % TO;
            ws[c][k][j] = g_Kt[((cg0 + c) * 7 + k) * OG + og0 + j];
        }
        __syncthreads();

#pragma unroll
        for (int c = 0; c < CC; c++) {
            float xr[3][6];
#pragma unroll
            for (int row = 0; row < 3; row++)
#pragma unroll
                for (int j = 0; j < 6; j++) xr[row][j] = xs[c][row][pxl + j];

#pragma unroll
            for (int k = 0; k < 7; k++) {
                const int py = hpy[k];
                const int px = hpx[k];
                float wv[8];
#pragma unroll
                for (int oo = 0; oo < 8; oo++) wv[oo] = ws[c][k][ogl + oo];
#pragma unroll
                for (int oo = 0; oo < 8; oo++)
#pragma unroll
                    for (int j = 0; j < 4; j++)
                        acc[oo][j] += wv[oo] * xr[py][j + px];
            }
        }
        __syncthreads();
    }

    // --- epilogue: add bias, store into res interior ---
    const int y_res = cy + 1;
#pragma unroll
    for (int oo = 0; oo < 8; oo++) {
        int og = og0 + ogl + oo;
        float bv = bias[og / 12];
        float* op = out + ((size_t)(b * OG + og) * HP + y_res) * WP + (x0 + 1 + pxl);
#pragma unroll
        for (int j = 0; j < 4; j++) op[j] = acc[oo][j] + bv;
    }
}

// ---------------------------------------------------------------------------
// Kernel 3: fill toroidal/group-twisted boundary from interior values
// res[b, o*12+t, y, x] = res[b, o*12+g', sy, sx]
//   x==0    -> sx=WP-2, dt=+1 ;  x==WP-1 -> sx=1, dt=-1 ; else sx=x, dt=0
//   y==0    -> sy=HP-2          ;  y==HP-1 -> sy=1         ; else sy=y
//   g' = f*6 + ((r+dt) mod 6)
// ---------------------------------------------------------------------------
__global__ void boundary_kernel(float* __restrict__ out) {
    const int PER = 2 * WP + 2 * HC;   // 772 boundary pixels per (b, og)
    int tid = blockIdx.x * blockDim.x + threadIdx.x;
    int total = B_ * OG * PER;
    if (tid >= total) return;

    int p   = tid % PER;
    int bog = tid / PER;
    int og  = bog % OG;
    int b   = bog / OG;

    int y, xx;
    if (p < WP)               { y = 0;      xx = p; }
    else if (p < 2 * WP)      { y = HP - 1; xx = p - WP; }
    else if (p < 2 * WP + HC) { xx = 0;      y = p - 2 * WP + 1; }
    else                      { xx = WP - 1; y = p - (2 * WP + HC) + 1; }

    int sx = xx, dt = 0;
    if (xx == 0)            { sx = WP - 2; dt = 1; }
    else if (xx == WP - 1)  { sx = 1;      dt = -1; }
    int sy = y;
    if (y == 0)             sy = HP - 2;
    else if (y == HP - 1)   sy = 1;

    int o = og / 12, t = og % 12;
    int f = t / 6,   r = t % 6;
    int gp = f * 6 + ((r + dt + 6) % 6);
    int og_src = o * 12 + gp;

    out[((size_t)(b * OG + og) * HP + y) * WP + xx] =
        out[((size_t)(b * OG + og_src) * HP + sy) * WP + sx];
}

// ---------------------------------------------------------------------------
extern "C" void kernel_launch(void* const* d_in, const int* in_sizes, int n_in,
                              void* d_out, int out_size) {
    (void)in_sizes; (void)n_in; (void)out_size;
    const float* x    = (const float*)d_in[0];
    const float* w    = (const float*)d_in[1];
    const float* bias = (const float*)d_in[2];
    float* out = (float*)d_out;

    prep_kernel<<<(CG * OG + 255) / 256, 256>>>(w);

    dim3 grid(WC / TX, HC, B_ * 3);   // (5, 64, 24)
    conv_kernel<<<grid, NTHREADS>>>(x, bias, out);

    int total = B_ * OG * (2 * WP + 2 * HC);
    boundary_kernel<<<(total + 255) / 256, 256>>>(out);
}

// round 3
// speedup vs baseline: 4.2126x; 4.2126x over previous
#include <cuda_runtime.h>
#include <cstdint>

// ---------------------------------------------------------------- constants
#define B_   8
#define CG   192
#define OG   192
#define HP   66
#define WP   322
#define HC   64
#define WC   320
#define KTOT 1536            // CG * 8 (7 hex taps + zero pad)
#define NCH  48              // KTOT / 32
#define NTHR 256

// Weights in mma-fragment layout: [chunk48][kstep4][n8blk24][lane32][2]
__device__ float g_Kt[NCH * 6144];

// ---------------------------------------------------------------- utils
__device__ __forceinline__ uint32_t tf32r(float f) {
    uint32_t r;
    asm("cvt.rna.tf32.f32 %0, %1;" : "=r"(r) : "f"(f));
    return r;
}
__device__ __forceinline__ uint32_t smem_u32(const void* p) {
    uint32_t a;
    asm("{ .reg .u64 t; cvta.to.shared.u64 t, %1; cvt.u32.u64 %0, t; }"
        : "=r"(a) : "l"(p));
    return a;
}

// ---------------------------------------------------------------- prep
// Expand w(O,Cin,12,7) via p6m group tables into g_Kt fragment layout,
// tf32-rounded. One thread per (og, cg) writes its 8 taps (tap7 = 0).
__global__ void prep_kernel(const float* __restrict__ w) {
    int tid = blockIdx.x * blockDim.x + threadIdx.x;
    if (tid >= OG * CG) return;
    int og = tid / CG;
    int cg = tid % CG;
    int o = og / 12, g = og % 12;
    int c = cg / 12, h = cg % 12;
    int fg = g / 6, rg = g % 6;
    int fh = h / 6, rh = h % 6;
    int f = fg ^ fh;
    int r = (fg == 0) ? ((rh - rg + 6) % 6) : ((rg - rh + 6) % 6);
    int p = f * 6 + r;
    const float* wp = w + ((o * 16 + c) * 12 + p) * 7;

    float vals[8];
    vals[0] = wp[0];
#pragma unroll
    for (int i = 0; i < 6; i++) {
        int src = (fg == 0) ? ((i - rg + 12) % 6) : ((rg - i + 12) % 6);
        vals[1 + i] = wp[1 + src];
    }
    vals[7] = 0.0f;

    int nb = og >> 3;
    int lane_hi = (og & 7) * 4;
#pragma unroll
    for (int t = 0; t < 8; t++) {
        int k = cg * 8 + t;
        int ch = k >> 5;
        int s  = (k >> 3) & 3;
        int kk = k & 7;
        int half = kk >> 2;
        int lane = lane_hi + (kk & 3);
        g_Kt[(size_t)(((ch * 4 + s) * 24 + nb) * 32 + lane) * 2 + half] =
            __uint_as_float(tf32r(vals[t]));
    }
}

// ---------------------------------------------------------------- conv
// SMEM: A 2 stages x 16KB, B 2 stages x 24KB, bias 768B
#define SMEM_B_OFF   32768
#define SMEM_BIAS    81920
#define SMEM_TOT     (81920 + 768)

__global__ void __launch_bounds__(NTHR, 1) conv_mma(
    const float* __restrict__ x,
    const float* __restrict__ bias,
    float* __restrict__ out)
{
    extern __shared__ char smem[];
    const uint32_t sb = smem_u32(smem);
    const int tid  = threadIdx.x;
    const int lane = tid & 31;
    const int wrp  = tid >> 5;
    const int wm   = wrp >> 2;      // 0..1
    const int wn   = wrp & 3;       // 0..3
    const int b    = blockIdx.z;
    const int cy0  = blockIdx.y * 2;
    const int cx0  = blockIdx.x * 64;

    if (tid < OG) ((float*)(smem + SMEM_BIAS))[tid] = bias[tid / 12];

    // per-thread A-build constants: kl = local k index 0..31
    const int kl  = tid >> 3;
    const int tap = kl & 7;
    const int cgl = kl >> 3;        // chunk-local cg 0..3 (== kstep S)
    const int S   = cgl;
    const int L   = (tid & 7) * 4 + (tap & 3);
    const int KH  = tap >> 2;
    int dy, dx;
    switch (tap) {
        case 0: dy = 1; dx = 1; break;
        case 1: dy = 0; dx = 0; break;
        case 2: dy = 0; dx = 1; break;
        case 3: dy = 1; dx = 2; break;
        case 4: dy = 2; dx = 2; break;
        case 5: dy = 2; dx = 1; break;
        case 6: dy = 1; dx = 0; break;
        default: dy = 1; dx = 1; break;   // zero-weight pad tap
    }
    const size_t plane = (size_t)HP * WP;
    const float* xbase = x + ((size_t)b * CG * HP + (cy0 + dy)) * WP
                       + (cx0 + dx) + (tid & 7);
    const uint32_t a_sts0 = sb + (uint32_t)(((S * 8) * 32 + L) * 16 + KH * 8);

    float v[16];

    float acc[4][6][4];
#pragma unroll
    for (int i = 0; i < 4; i++)
#pragma unroll
        for (int j = 0; j < 6; j++)
#pragma unroll
            for (int q = 0; q < 4; q++) acc[i][j][q] = 0.f;

    // ---- stage 0 fill ----
    {
        const float* xp = xbase + (size_t)cgl * plane;   // ch=0
#pragma unroll
        for (int e = 0; e < 16; e++)
            v[e] = __ldg(xp + (e >> 3) * WP + 8 * (e & 7));

        const float* src = g_Kt + (size_t)tid * 4;       // ch=0
        uint32_t dst = sb + SMEM_B_OFF + tid * 16;
#pragma unroll
        for (int i = 0; i < 6; i++)
            asm volatile("cp.async.cg.shared.global [%0], [%1], 16;"
                         :: "r"(dst + i * 4096), "l"(src + i * 1024) : "memory");
        asm volatile("cp.async.commit_group;" ::: "memory");

#pragma unroll
        for (int j = 0; j < 8; j++) {
            uint32_t va = tf32r(v[2 * j]), vb = tf32r(v[2 * j + 1]);
            asm volatile("st.shared.v2.b32 [%0], {%1,%2};"
                         :: "r"(a_sts0 + j * 512), "r"(va), "r"(vb));
        }
        asm volatile("cp.async.wait_group 0;" ::: "memory");
        __syncthreads();
    }

    // ---- main K loop ----
    for (int ch = 0; ch < NCH; ch++) {
        const int s = ch & 1;
        if (ch + 1 < NCH) {
            // prefetch next A chunk into registers (latency under MMAs)
            const float* xp = xbase + (size_t)((ch + 1) * 4 + cgl) * plane;
#pragma unroll
            for (int e = 0; e < 16; e++)
                v[e] = __ldg(xp + (e >> 3) * WP + 8 * (e & 7));
            // stream next B chunk
            const float* src = g_Kt + (size_t)(ch + 1) * 6144 + tid * 4;
            uint32_t dst = sb + SMEM_B_OFF + (s ^ 1) * 24576 + tid * 16;
#pragma unroll
            for (int i = 0; i < 6; i++)
                asm volatile("cp.async.cg.shared.global [%0], [%1], 16;"
                             :: "r"(dst + i * 4096), "l"(src + i * 1024) : "memory");
            asm volatile("cp.async.commit_group;" ::: "memory");
        }

        const uint32_t Ab = sb + s * 16384 + (uint32_t)((wm * 4 * 32 + lane) * 16);
        const uint32_t Bb = sb + SMEM_B_OFF + s * 24576
                          + (uint32_t)((wn * 6 * 32 + lane) * 8);
#pragma unroll
        for (int ks = 0; ks < 4; ks++) {
            uint32_t a[4][4];
#pragma unroll
            for (int mf = 0; mf < 4; mf++)
                asm volatile("ld.shared.v4.b32 {%0,%1,%2,%3}, [%4];"
                    : "=r"(a[mf][0]), "=r"(a[mf][1]), "=r"(a[mf][2]), "=r"(a[mf][3])
                    : "r"(Ab + ks * 4096 + mf * 512));
            uint32_t bf[6][2];
#pragma unroll
            for (int nf = 0; nf < 6; nf++)
                asm volatile("ld.shared.v2.b32 {%0,%1}, [%2];"
                    : "=r"(bf[nf][0]), "=r"(bf[nf][1])
                    : "r"(Bb + ks * 6144 + nf * 256));
#pragma unroll
            for (int mf = 0; mf < 4; mf++)
#pragma unroll
                for (int nf = 0; nf < 6; nf++)
                    asm volatile(
                        "mma.sync.aligned.m16n8k8.row.col.f32.tf32.tf32.f32 "
                        "{%0,%1,%2,%3}, {%4,%5,%6,%7}, {%8,%9}, {%0,%1,%2,%3};"
                        : "+f"(acc[mf][nf][0]), "+f"(acc[mf][nf][1]),
                          "+f"(acc[mf][nf][2]), "+f"(acc[mf][nf][3])
                        : "r"(a[mf][0]), "r"(a[mf][1]), "r"(a[mf][2]), "r"(a[mf][3]),
                          "r"(bf[nf][0]), "r"(bf[nf][1]));
        }

        if (ch + 1 < NCH) {
            uint32_t base = a_sts0 + (s ^ 1) * 16384;
#pragma unroll
            for (int j = 0; j < 8; j++) {
                uint32_t va = tf32r(v[2 * j]), vb = tf32r(v[2 * j + 1]);
                asm volatile("st.shared.v2.b32 [%0], {%1,%2};"
                             :: "r"(base + j * 512), "r"(va), "r"(vb));
            }
        }
        asm volatile("cp.async.wait_group 0;" ::: "memory");
        __syncthreads();
    }

    // ---- epilogue: bias + store interior ----
    const float* bs = (const float*)(smem + SMEM_BIAS);
#pragma unroll
    for (int mf = 0; mf < 4; mf++) {
#pragma unroll
        for (int half = 0; half < 2; half++) {
            int m  = wm * 64 + mf * 16 + (lane >> 2) + half * 8;
            int ry = m >> 6, rx = m & 63;
            float* orow = out + ((size_t)b * OG * HP + (size_t)(cy0 + ry + 1)) * WP
                        + (cx0 + rx + 1);
#pragma unroll
            for (int nf = 0; nf < 6; nf++) {
                int og = wn * 48 + nf * 8 + (lane & 3) * 2;
                float d0 = acc[mf][nf][half * 2 + 0] + bs[og];
                float d1 = acc[mf][nf][half * 2 + 1] + bs[og + 1];
                orow[(size_t)og * plane]       = d0;
                orow[(size_t)(og + 1) * plane] = d1;
            }
        }
    }
}

// ---------------------------------------------------------------- boundary
__global__ void boundary_kernel(float* __restrict__ out) {
    const int PER = 2 * WP + 2 * HC;   // 772
    int tid = blockIdx.x * blockDim.x + threadIdx.x;
    int total = B_ * OG * PER;
    if (tid >= total) return;

    int p   = tid % PER;
    int bog = tid / PER;
    int og  = bog % OG;
    int b   = bog / OG;

    int y, xx;
    if (p < WP)               { y = 0;      xx = p; }
    else if (p < 2 * WP)      { y = HP - 1; xx = p - WP; }
    else if (p < 2 * WP + HC) { xx = 0;      y = p - 2 * WP + 1; }
    else                      { xx = WP - 1; y = p - (2 * WP + HC) + 1; }

    int sx = xx, dt = 0;
    if (xx == 0)           { sx = WP - 2; dt = 1; }
    else if (xx == WP - 1) { sx = 1;      dt = -1; }
    int sy = y;
    if (y == 0)            sy = HP - 2;
    else if (y == HP - 1)  sy = 1;

    int o = og / 12, t = og % 12;
    int f = t / 6,   rr = t % 6;
    int gp = f * 6 + ((rr + dt + 6) % 6);
    int og_src = o * 12 + gp;

    out[((size_t)(b * OG + og) * HP + y) * WP + xx] =
        out[((size_t)(b * OG + og_src) * HP + sy) * WP + sx];
}

// ---------------------------------------------------------------- launch
extern "C" void kernel_launch(void* const* d_in, const int* in_sizes, int n_in,
                              void* d_out, int out_size) {
    (void)in_sizes; (void)n_in; (void)out_size;
    const float* x    = (const float*)d_in[0];
    const float* w    = (const float*)d_in[1];
    const float* bias = (const float*)d_in[2];
    float* out = (float*)d_out;

    cudaFuncSetAttribute(conv_mma, cudaFuncAttributeMaxDynamicSharedMemorySize,
                         SMEM_TOT);

    prep_kernel<<<(OG * CG + 255) / 256, 256>>>(w);

    dim3 grid(WC / 64, HC / 2, B_);   // (5, 32, 8) = 1280 CTAs
    conv_mma<<<grid, NTHR, SMEM_TOT>>>(x, bias, out);

    int total = B_ * OG * (2 * WP + 2 * HC);
    boundary_kernel<<<(total + 255) / 256, 256>>>(out);
}

// round 4
// speedup vs baseline: 4.9408x; 1.1729x over previous
#include <cuda_runtime.h>
#include <cuda_fp16.h>
#include <cstdint>

// ---------------------------------------------------------------- constants
#define B_   8
#define CG   192
#define OG   192
#define HP   66
#define WP   322
#define HC   64
#define WC   320
#define KTOT 1344            // CG * 7 hex taps (no pad)
#define NCH  42              // KTOT / 32
#define NTHR 256

// Weights (half) in mma-fragment layout:
// [chunk42][ks2][nb24][lane32][4 halves]  (reg*2 + half)
__device__ __half g_Kt[NCH * 6144];

// tap -> offset (dy*WP + dx) for hex positions
__constant__ int c_off[7] = {WP + 1, 0, 1, WP + 2, 2 * WP + 2, 2 * WP + 1, WP};

// ---------------------------------------------------------------- utils
__device__ __forceinline__ uint32_t smem_u32(const void* p) {
    uint32_t a;
    asm("{ .reg .u64 t; cvta.to.shared.u64 t, %1; cvt.u32.u64 %0, t; }"
        : "=r"(a) : "l"(p));
    return a;
}

// ---------------------------------------------------------------- prep
// Expand w(O,Cin,12,7) via p6m group tables into g_Kt fragment layout (half).
__global__ void prep_kernel(const float* __restrict__ w) {
    int tid = blockIdx.x * blockDim.x + threadIdx.x;
    if (tid >= OG * CG) return;
    int og = tid / CG;
    int cg = tid % CG;
    int o = og / 12, g = og % 12;
    int c = cg / 12, h = cg % 12;
    int fg = g / 6, rg = g % 6;
    int fh = h / 6, rh = h % 6;
    int f = fg ^ fh;
    int r = (fg == 0) ? ((rh - rg + 6) % 6) : ((rg - rh + 6) % 6);
    int p = f * 6 + r;
    const float* wp = w + ((o * 16 + c) * 12 + p) * 7;

    float vals[7];
    vals[0] = wp[0];
#pragma unroll
    for (int i = 0; i < 6; i++) {
        int src = (fg == 0) ? ((i - rg + 12) % 6) : ((rg - i + 12) % 6);
        vals[1 + i] = wp[1 + src];
    }

    int nb = og >> 3;
    int n  = og & 7;
#pragma unroll
    for (int t = 0; t < 7; t++) {
        int k    = cg * 7 + t;
        int ch   = k >> 5;
        int kk   = k & 31;
        int ks   = kk >> 4;
        int kk16 = kk & 15;
        int lane = n * 4 + ((kk16 & 7) >> 1);
        int reg  = kk16 >> 3;
        int half = kk16 & 1;
        g_Kt[(size_t)(((ch * 2 + ks) * 24 + nb) * 32 + lane) * 4 + reg * 2 + half] =
            __float2half_rn(vals[t]);
    }
}

// ---------------------------------------------------------------- conv
// SMEM: A 2 stages x 8KB at 0 ; B 2 stages x 12KB at 16384 ; bias at 40960
#define SMEM_B_OFF 16384
#define SMEM_BIAS  40960
#define SMEM_TOT   (40960 + 768)

__global__ void __launch_bounds__(NTHR, 1) conv_mma(
    const float* __restrict__ x,
    const float* __restrict__ bias,
    float* __restrict__ out)
{
    extern __shared__ char smem[];
    const uint32_t sb = smem_u32(smem);
    const int tid  = threadIdx.x;
    const int lane = tid & 31;
    const int wrp  = tid >> 5;
    const int wm   = wrp >> 2;      // 0..1
    const int wn   = wrp & 3;       // 0..3
    const int b    = blockIdx.z;
    const int cy0  = blockIdx.y * 2;
    const int cx0  = blockIdx.x * 64;

    if (tid < OG) ((float*)(smem + SMEM_BIAS))[tid] = bias[tid / 12];

    // ---- A-build thread constants ----
    const int kp  = tid >> 4;       // 0..15 : k pair (2*kp, 2*kp+1) within chunk
    const int pxi = tid & 15;       // 16 pixel columns, 8 pixels each
    // STS address components (mb = e in the store loop)
    const int s_lane = (pxi & 7) * 4 + (kp & 3);
    const int s_reg  = (pxi >> 3) + ((kp >> 2) & 1) * 2;
    const uint32_t a_sts0 = sb + (uint32_t)((kp >> 3) * 4096 + s_lane * 16 + s_reg * 4);

    const size_t plane = (size_t)HP * WP;
    const float* xb = x + (size_t)b * CG * plane + (size_t)cy0 * WP + cx0 + pxi;

    uint32_t v[8];

    float acc[4][6][4];
#pragma unroll
    for (int i = 0; i < 4; i++)
#pragma unroll
        for (int j = 0; j < 6; j++)
#pragma unroll
            for (int q = 0; q < 4; q++) acc[i][j][q] = 0.f;

    // ---- helpers as macros (keep regs tight) ----
#define LOAD_A_CHUNK(ch)                                                      \
    do {                                                                      \
        int k0 = (ch) * 32 + kp * 2;                                          \
        int k1 = k0 + 1;                                                      \
        const float* p0 = xb + (size_t)(k0 / 7) * plane + c_off[k0 % 7];      \
        const float* p1 = xb + (size_t)(k1 / 7) * plane + c_off[k1 % 7];      \
        _Pragma("unroll")                                                     \
        for (int e = 0; e < 8; e++) {                                         \
            int off = (e >> 2) * WP + (e & 3) * 16;                           \
            float f0 = __ldg(p0 + off);                                       \
            float f1 = __ldg(p1 + off);                                       \
            __half2 hh = __halves2half2(__float2half_rn(f0), __float2half_rn(f1)); \
            v[e] = *(uint32_t*)&hh;                                           \
        }                                                                     \
    } while (0)

#define STORE_A_CHUNK(stage)                                                  \
    do {                                                                      \
        uint32_t base = a_sts0 + (stage) * 8192;                              \
        _Pragma("unroll")                                                     \
        for (int e = 0; e < 8; e++)                                           \
            asm volatile("st.shared.b32 [%0], %1;"                            \
                         :: "r"(base + e * 512), "r"(v[e]));                  \
    } while (0)

#define LOAD_B_CHUNK(ch, stage)                                               \
    do {                                                                      \
        const __half* src = g_Kt + (size_t)(ch) * 6144 + tid * 8;             \
        uint32_t dst = sb + SMEM_B_OFF + (stage) * 12288 + tid * 16;          \
        _Pragma("unroll")                                                     \
        for (int i = 0; i < 3; i++)                                           \
            asm volatile("cp.async.cg.shared.global [%0], [%1], 16;"          \
                         :: "r"(dst + i * 4096), "l"(src + i * 2048) : "memory"); \
        asm volatile("cp.async.commit_group;" ::: "memory");                  \
    } while (0)

    // ---- stage 0 fill ----
    LOAD_A_CHUNK(0);
    LOAD_B_CHUNK(0, 0);
    STORE_A_CHUNK(0);
    asm volatile("cp.async.wait_group 0;" ::: "memory");
    __syncthreads();

    // ---- main K loop ----
    for (int ch = 0; ch < NCH; ch++) {
        const int s = ch & 1;
        if (ch + 1 < NCH) {
            LOAD_A_CHUNK(ch + 1);
            LOAD_B_CHUNK(ch + 1, s ^ 1);
        }

        const uint32_t Ab = sb + s * 8192 + (uint32_t)((wm * 4) * 512 + lane * 16);
        const uint32_t Bb = sb + SMEM_B_OFF + s * 12288
                          + (uint32_t)((wn * 6) * 256 + lane * 8);
#pragma unroll
        for (int ks = 0; ks < 2; ks++) {
            uint32_t a[4][4];
#pragma unroll
            for (int mf = 0; mf < 4; mf++)
                asm volatile("ld.shared.v4.b32 {%0,%1,%2,%3}, [%4];"
                    : "=r"(a[mf][0]), "=r"(a[mf][1]), "=r"(a[mf][2]), "=r"(a[mf][3])
                    : "r"(Ab + ks * 4096 + mf * 512));
            uint32_t bf[6][2];
#pragma unroll
            for (int nf = 0; nf < 6; nf++)
                asm volatile("ld.shared.v2.b32 {%0,%1}, [%2];"
                    : "=r"(bf[nf][0]), "=r"(bf[nf][1])
                    : "r"(Bb + ks * 6144 + nf * 256));
#pragma unroll
            for (int mf = 0; mf < 4; mf++)
#pragma unroll
                for (int nf = 0; nf < 6; nf++)
                    asm volatile(
                        "mma.sync.aligned.m16n8k16.row.col.f32.f16.f16.f32 "
                        "{%0,%1,%2,%3}, {%4,%5,%6,%7}, {%8,%9}, {%0,%1,%2,%3};"
                        : "+f"(acc[mf][nf][0]), "+f"(acc[mf][nf][1]),
                          "+f"(acc[mf][nf][2]), "+f"(acc[mf][nf][3])
                        : "r"(a[mf][0]), "r"(a[mf][1]), "r"(a[mf][2]), "r"(a[mf][3]),
                          "r"(bf[nf][0]), "r"(bf[nf][1]));
        }

        if (ch + 1 < NCH) STORE_A_CHUNK(s ^ 1);
        asm volatile("cp.async.wait_group 0;" ::: "memory");
        __syncthreads();
    }

    // ---- epilogue: bias + store interior ----
    const float* bs = (const float*)(smem + SMEM_BIAS);
#pragma unroll
    for (int mf = 0; mf < 4; mf++) {
#pragma unroll
        for (int half = 0; half < 2; half++) {
            int m  = wm * 64 + mf * 16 + (lane >> 2) + half * 8;
            int ry = m >> 6, rx = m & 63;
            float* orow = out + ((size_t)b * OG * HP + (size_t)(cy0 + ry + 1)) * WP
                        + (cx0 + rx + 1);
#pragma unroll
            for (int nf = 0; nf < 6; nf++) {
                int og = wn * 48 + nf * 8 + (lane & 3) * 2;
                orow[(size_t)og * plane]       = acc[mf][nf][half * 2 + 0] + bs[og];
                orow[(size_t)(og + 1) * plane] = acc[mf][nf][half * 2 + 1] + bs[og + 1];
            }
        }
    }
}

// ---------------------------------------------------------------- boundary
__global__ void boundary_kernel(float* __restrict__ out) {
    const int PER = 2 * WP + 2 * HC;   // 772
    int tid = blockIdx.x * blockDim.x + threadIdx.x;
    int total = B_ * OG * PER;
    if (tid >= total) return;

    int p   = tid % PER;
    int bog = tid / PER;
    int og  = bog % OG;
    int b   = bog / OG;

    int y, xx;
    if (p < WP)               { y = 0;      xx = p; }
    else if (p < 2 * WP)      { y = HP - 1; xx = p - WP; }
    else if (p < 2 * WP + HC) { xx = 0;      y = p - 2 * WP + 1; }
    else                      { xx = WP - 1; y = p - (2 * WP + HC) + 1; }

    int sx = xx, dt = 0;
    if (xx == 0)           { sx = WP - 2; dt = 1; }
    else if (xx == WP - 1) { sx = 1;      dt = -1; }
    int sy = y;
    if (y == 0)            sy = HP - 2;
    else if (y == HP - 1)  sy = 1;

    int o = og / 12, t = og % 12;
    int f = t / 6,   rr = t % 6;
    int gp = f * 6 + ((rr + dt + 6) % 6);
    int og_src = o * 12 + gp;

    out[((size_t)(b * OG + og) * HP + y) * WP + xx] =
        out[((size_t)(b * OG + og_src) * HP + sy) * WP + sx];
}

// ---------------------------------------------------------------- launch
extern "C" void kernel_launch(void* const* d_in, const int* in_sizes, int n_in,
                              void* d_out, int out_size) {
    (void)in_sizes; (void)n_in; (void)out_size;
    const float* x    = (const float*)d_in[0];
    const float* w    = (const float*)d_in[1];
    const float* bias = (const float*)d_in[2];
    float* out = (float*)d_out;

    cudaFuncSetAttribute(conv_mma, cudaFuncAttributeMaxDynamicSharedMemorySize,
                         SMEM_TOT);

    prep_kernel<<<(OG * CG + 255) / 256, 256>>>(w);

    dim3 grid(WC / 64, HC / 2, B_);   // (5, 32, 8) = 1280 CTAs
    conv_mma<<<grid, NTHR, SMEM_TOT>>>(x, bias, out);

    int total = B_ * OG * (2 * WP + 2 * HC);
    boundary_kernel<<<(total + 255) / 256, 256>>>(out);
}